// round 1
// baseline (speedup 1.0000x reference)
#include <cuda_runtime.h>
#include <cstdint>

#define D      128
#define KC     1024
#define MLVL   4
#define TM     32        // rows per block
#define TKC    64        // codes per smem chunk
#define NCH    (KC / TKC)
#define NTHR   256
#define MAXBLK 4096

// smem layout (floats):
//   rs   [D][TM]      = 4096
//   cs   [D][TKC]     = 8192
//   e2s  [TKC]        = 64
//   r2s  [TM]         = 32
//   r2p  [8][TM]      = 256
//   idxs [MLVL][TM]   = 128 (ints)
//   dred [NTHR] doubles at byte offset 51072 (8B aligned)
#define SMEM_FLOATS (4096 + 8192 + 64 + 32 + 256 + 128)
#define SMEM_BYTES  (SMEM_FLOATS * 4 + NTHR * 8)   // 53120

__device__ float  g_e2[MLVL * KC];
__device__ double g_part[MAXBLK];

// ---------------- packed f32x2 helpers ----------------
__device__ __forceinline__ unsigned long long pack2(float a, float b) {
    unsigned long long r;
    asm("mov.b64 %0, {%1, %2};" : "=l"(r) : "f"(a), "f"(b));
    return r;
}
__device__ __forceinline__ unsigned long long bcast2(float a) {
    unsigned long long r;
    asm("mov.b64 %0, {%1, %1};" : "=l"(r) : "f"(a));
    return r;
}
__device__ __forceinline__ void fma2(unsigned long long& acc,
                                     unsigned long long a,
                                     unsigned long long b) {
    asm("fma.rn.f32x2 %0, %1, %2, %3;" : "=l"(acc) : "l"(a), "l"(b), "l"(acc));
}
__device__ __forceinline__ void unpack2(unsigned long long v, float& lo, float& hi) {
    asm("mov.b64 {%0, %1}, %2;" : "=f"(lo), "=f"(hi) : "l"(v));
}

// ---------------- e2[k] = sum_d cb[k][d]^2 ----------------
__global__ void e2_kernel(const float* __restrict__ cb) {
    int c = blockIdx.x * blockDim.x + threadIdx.x;
    if (c < MLVL * KC) {
        const float* row = cb + (size_t)c * D;
        float s = 0.f;
#pragma unroll
        for (int d = 0; d < D; d++) s = __fmaf_rn(row[d], row[d], s);
        g_e2[c] = s;
    }
}

// ---------------- main RVQ kernel ----------------
__global__ __launch_bounds__(NTHR, 4)
void rvq_kernel(const float* __restrict__ x, const float* __restrict__ cb,
                float* __restrict__ y, int nrows) {
    extern __shared__ float smem[];
    float* rs  = smem;                    // [D][TM]
    float* cs  = rs + D * TM;             // [D][TKC]
    float* e2s = cs + D * TKC;            // [TKC]
    float* r2s = e2s + TKC;               // [TM]
    float* r2p = r2s + TM;                // [8][TM]
    int*   idxs = (int*)(r2p + 8 * TM);   // [MLVL][TM]
    double* dred = (double*)(smem + SMEM_FLOATS);  // [NTHR]

    const int t  = threadIdx.x;
    const int tx = t & 15;                // code direction (16)
    const int ty = t >> 4;                // row direction  (16)  -> rows ty*2, ty*2+1
    const int rowBase = blockIdx.x * TM;
    if (rowBase >= nrows) return;
    const float* xr = x + (size_t)rowBase * D;

    // element mapping for load/update passes: fixed row per thread
    const int rloc  = t & 31;             // row 0..31
    const int dbase = t >> 5;             // 0..7 ; d = dbase + 8*j, j<16

    double lsum = 0.0;

    // ---- load x into transposed residual tile + initial r2 ----
    {
        float p = 0.f;
#pragma unroll
        for (int j = 0; j < 16; j++) {
            int d = dbase + 8 * j;
            float v = xr[(size_t)rloc * D + d];
            rs[d * TM + rloc] = v;
            p = __fmaf_rn(v, v, p);
        }
        r2p[dbase * TM + rloc] = p;
    }
    __syncthreads();
    if (t < TM) {
        float s = r2p[t];
#pragma unroll
        for (int g = 1; g < 8; g++) s = __fadd_rn(s, r2p[g * TM + t]);
        r2s[t] = s;
    }
    __syncthreads();

    const float2* rsp = reinterpret_cast<const float2*>(rs) + ty;  // rs[d][2*ty] : index d*16
    const float4* csp = reinterpret_cast<const float4*>(cs) + tx;  // cs[d][4*tx] : index d*16

    for (int lvl = 0; lvl < MLVL; lvl++) {
        const float* cbl = cb + (size_t)lvl * KC * D;
        const float* e2l = g_e2 + lvl * KC;
        const float r2r0 = r2s[ty * 2 + 0];
        const float r2r1 = r2s[ty * 2 + 1];

        float bd0 = 3.4e38f, bd1 = 3.4e38f;
        int   bi0 = 0,       bi1 = 0;

        for (int c = 0; c < NCH; c++) {
            const int k0 = c * TKC;
            __syncthreads();   // previous chunk compute done before overwriting cs
            // load codebook chunk transposed: kl = t&63, d = (t>>6)+4j
            {
                const int kl = t & 63, db2 = t >> 6;
                const float* src = cbl + (size_t)(k0 + kl) * D;
#pragma unroll
                for (int j = 0; j < 32; j++) {
                    int d = db2 + 4 * j;
                    cs[d * TKC + kl] = src[d];
                }
            }
            if (t < TKC) e2s[t] = e2l[k0 + t];
            __syncthreads();

            unsigned long long a00 = 0ull, a01 = 0ull, a10 = 0ull, a11 = 0ull;
#pragma unroll 16
            for (int d = 0; d < D; d++) {
                float2 rv = rsp[d * 16];
                float4 cv = csp[d * 16];
                unsigned long long cp0 = pack2(cv.x, cv.y);
                unsigned long long cp1 = pack2(cv.z, cv.w);
                unsigned long long rr0 = bcast2(rv.x);
                unsigned long long rr1 = bcast2(rv.y);
                fma2(a00, rr0, cp0);
                fma2(a01, rr0, cp1);
                fma2(a10, rr1, cp0);
                fma2(a11, rr1, cp1);
            }
            float dots0[4], dots1[4];
            unpack2(a00, dots0[0], dots0[1]);
            unpack2(a01, dots0[2], dots0[3]);
            unpack2(a10, dots1[0], dots1[1]);
            unpack2(a11, dots1[2], dots1[3]);

            const int kb = k0 + tx * 4;
#pragma unroll
            for (int j = 0; j < 4; j++) {
                float e2v = e2s[tx * 4 + j];
                // dist = fl( fl(r2+e2) - 2*dot )  — matches reference association
                float s0 = __fadd_rn(r2r0, e2v);
                float d0 = __fmaf_rn(-2.0f, dots0[j], s0);
                if (d0 < bd0) { bd0 = d0; bi0 = kb + j; }   // strict < => first min
                float s1 = __fadd_rn(r2r1, e2v);
                float d1 = __fmaf_rn(-2.0f, dots1[j], s1);
                if (d1 < bd1) { bd1 = d1; bi1 = kb + j; }
            }
        }

        // reduce argmin across the 16 tx lanes (first-min tiebreak by index)
#pragma unroll
        for (int off = 8; off >= 1; off >>= 1) {
            float od = __shfl_xor_sync(0xffffffffu, bd0, off);
            int   oi = __shfl_xor_sync(0xffffffffu, bi0, off);
            if (od < bd0 || (od == bd0 && oi < bi0)) { bd0 = od; bi0 = oi; }
            od = __shfl_xor_sync(0xffffffffu, bd1, off);
            oi = __shfl_xor_sync(0xffffffffu, bi1, off);
            if (od < bd1 || (od == bd1 && oi < bi1)) { bd1 = od; bi1 = oi; }
        }
        if (tx == 0) {
            idxs[lvl * TM + ty * 2 + 0] = bi0;
            idxs[lvl * TM + ty * 2 + 1] = bi1;
        }
        __syncthreads();

        // residual update + r2 recompute + loss partial
        {
            const int qi = idxs[lvl * TM + rloc];
            const float* qrow = cbl + (size_t)qi * D;
            float p = 0.f;
#pragma unroll
            for (int j = 0; j < 16; j++) {
                int d = dbase + 8 * j;
                float v = __fsub_rn(rs[d * TM + rloc], qrow[d]);  // residual -= q  (fp32, matches ref)
                rs[d * TM + rloc] = v;
                p = __fmaf_rn(v, v, p);
                lsum += (double)v * (double)v;   // (q - r_pre)^2 == r_post^2
            }
            r2p[dbase * TM + rloc] = p;
        }
        __syncthreads();
        if (t < TM) {
            float s = r2p[t];
#pragma unroll
            for (int g = 1; g < 8; g++) s = __fadd_rn(s, r2p[g * TM + t]);
            r2s[t] = s;
        }
        __syncthreads();
    }

    // ---- y = x + (q_sum - x), q_sum rebuilt in reference order ----
    {
        float* yb = y + (size_t)rowBase * D;
        const int d = t & 127;
        const int rb = t >> 7;    // r = rb + 2*j
#pragma unroll
        for (int j = 0; j < 16; j++) {
            int r = rb + 2 * j;
            int i0 = idxs[0 * TM + r];
            int i1 = idxs[1 * TM + r];
            int i2 = idxs[2 * TM + r];
            int i3 = idxs[3 * TM + r];
            float q = cb[((size_t)0 * KC + i0) * D + d];
            q = __fadd_rn(q, cb[((size_t)1 * KC + i1) * D + d]);
            q = __fadd_rn(q, cb[((size_t)2 * KC + i2) * D + d]);
            q = __fadd_rn(q, cb[((size_t)3 * KC + i3) * D + d]);
            float xv = xr[(size_t)r * D + d];
            yb[(size_t)r * D + d] = __fadd_rn(xv, __fsub_rn(q, xv));
        }
    }

    // ---- deterministic block loss reduction ----
    dred[t] = lsum;
    __syncthreads();
#pragma unroll
    for (int s = NTHR / 2; s > 0; s >>= 1) {
        if (t < s) dred[t] += dred[t + s];
        __syncthreads();
    }
    if (t == 0) g_part[blockIdx.x] = dred[0];
}

// ---------------- final loss scalar ----------------
__global__ void loss_kernel(float* out, int nblocks, long long nelems) {
    __shared__ double sh[128];
    double s = 0.0;
    for (int b = threadIdx.x; b < nblocks; b += 128) s += g_part[b];
    sh[threadIdx.x] = s;
    __syncthreads();
    for (int st = 64; st > 0; st >>= 1) {
        if (threadIdx.x < st) sh[threadIdx.x] += sh[threadIdx.x + st];
        __syncthreads();
    }
    if (threadIdx.x == 0)
        out[0] = (float)(1.25 * (sh[0] / (double)nelems));
}

extern "C" void kernel_launch(void* const* d_in, const int* in_sizes, int n_in,
                              void* d_out, int out_size) {
    const float* x  = (const float*)d_in[0];
    const float* cb = (const float*)d_in[1];
    float* y = (float*)d_out;

    const long long xelems = (long long)in_sizes[0];    // N*D
    const int nrows   = (int)(xelems / D);
    const int nblocks = (nrows + TM - 1) / TM;

    cudaFuncSetAttribute(rvq_kernel, cudaFuncAttributeMaxDynamicSharedMemorySize, SMEM_BYTES);

    e2_kernel<<<(MLVL * KC + 255) / 256, 256>>>(cb);
    rvq_kernel<<<nblocks, NTHR, SMEM_BYTES>>>(x, cb, y, nrows);
    if ((long long)out_size > xelems)
        loss_kernel<<<1, 128>>>(y + xelems, nblocks, xelems);
}

// round 4
// speedup vs baseline: 2.4993x; 2.4993x over previous
#include <cuda_runtime.h>
#include <cstdint>

#define D      128
#define D4     32
#define KC     1024
#define MLVL   4
#define TM     64          // rows per block
#define TKC    32          // codes per chunk
#define NCH    (KC / TKC)  // 32
#define NTHR   128
#define RST    132         // padded row stride (floats): conflict-free LDS.128
#define MAXBLK 4096

__device__ double g_part[MAXBLK];

// smem layout (float offsets)
#define OFF_CS   (TM * RST)                 // 8448
#define OFF_E2S  (OFF_CS + TKC * RST)       // 12672
#define OFF_R2S  (OFF_E2S + TKC)            // 12704
#define OFF_SD   (OFF_R2S + TM)             // 12768
#define OFF_SI   (OFF_SD + 2 * TM)          // 12896
#define OFF_IDX  (OFF_SI + 2 * TM)          // 13024
#define SMEM_FLOATS (OFF_IDX + MLVL * TM)   // 13280
#define SMEM_BYTES  (SMEM_FLOATS * 4 + NTHR * 8)  // 54144

__device__ __forceinline__ void fma2(unsigned long long& acc,
                                     unsigned long long a,
                                     unsigned long long b) {
    asm("fma.rn.f32x2 %0, %1, %2, %3;" : "=l"(acc) : "l"(a), "l"(b), "l"(acc));
}
__device__ __forceinline__ void unpack2(unsigned long long v, float& lo, float& hi) {
    asm("mov.b64 {%0, %1}, %2;" : "=f"(lo), "=f"(hi) : "l"(v));
}

__global__ __launch_bounds__(NTHR, 4)
void rvq_kernel(const float* __restrict__ x, const float* __restrict__ cb,
                float* __restrict__ y, int nrows) {
    extern __shared__ float smem[];
    float* rs   = smem;                     // [TM][RST]
    float* cs   = smem + OFF_CS;            // [TKC][RST]
    float* e2s  = smem + OFF_E2S;           // [TKC]
    float* r2s  = smem + OFF_R2S;           // [TM]
    float* sd   = smem + OFF_SD;            // [2][TM]
    int*   si   = (int*)(smem + OFF_SI);    // [2][TM]
    int*   idxs = (int*)(smem + OFF_IDX);   // [MLVL][TM]
    double* dred = (double*)(smem + SMEM_FLOATS);  // [NTHR]

    const int t    = threadIdx.x;
    const int w    = t >> 5;
    const int l    = t & 31;
    const int ty   = l >> 2;               // 0..7
    const int txc  = l & 3;                // 0..3
    const int half = w & 1;
    const int rowg = 8 * (w >> 1) + ty;    // 0..15 -> rows 4*rowg..+3
    const int kbase = 16 * half;

    const int rowBase = blockIdx.x * TM;
    if (rowBase >= nrows) return;
    const float4* x4  = (const float4*)(x + (size_t)rowBase * D);
    const float4* cb4 = (const float4*)cb;

    double lsum = 0.0;

    // ---- initial residual load + r2 ----
#pragma unroll
    for (int i2 = 0; i2 < 16; i2++) {
        int row = w + 4 * i2;
        float4 v = x4[(size_t)row * D4 + l];
        *(float4*)&rs[row * RST + 4 * l] = v;
        float p = __fmaf_rn(v.x, v.x, 0.f);
        p = __fmaf_rn(v.y, v.y, p);
        p = __fmaf_rn(v.z, v.z, p);
        p = __fmaf_rn(v.w, v.w, p);
#pragma unroll
        for (int off = 16; off >= 1; off >>= 1)
            p = __fadd_rn(p, __shfl_xor_sync(0xffffffffu, p, off));
        if (l == 0) r2s[row] = p;
    }
    __syncthreads();

    const ulonglong2* rvp = (const ulonglong2*)&rs[(4 * rowg) * RST];
    const ulonglong2* cvp = (const ulonglong2*)&cs[(kbase + txc) * RST];

    // ---- prefetch chunk (lvl=0, c=0) into registers ----
    float4 v[8];
#pragma unroll
    for (int i = 0; i < 8; i++) v[i] = cb4[t + NTHR * i];

    for (int lvl = 0; lvl < MLVL; lvl++) {
        const float4* cbl4 = cb4 + (size_t)lvl * KC * D4;

        float r2r[4];
#pragma unroll
        for (int i = 0; i < 4; i++) r2r[i] = r2s[4 * rowg + i];

        float bd[4]; int bi[4];
#pragma unroll
        for (int i = 0; i < 4; i++) { bd[i] = 3.4e38f; bi[i] = 0; }

        for (int c = 0; c < NCH; c++) {
            // e2 for codes w+4i from prefetched regs (warp w owns codes == w mod 4)
            float e2v[8];
#pragma unroll
            for (int i = 0; i < 8; i++) {
                float p = __fmaf_rn(v[i].x, v[i].x, 0.f);
                p = __fmaf_rn(v[i].y, v[i].y, p);
                p = __fmaf_rn(v[i].z, v[i].z, p);
                p = __fmaf_rn(v[i].w, v[i].w, p);
#pragma unroll
                for (int off = 16; off >= 1; off >>= 1)
                    p = __fadd_rn(p, __shfl_xor_sync(0xffffffffu, p, off));
                e2v[i] = p;
            }
            __syncthreads();     // previous chunk compute done -> cs/e2s free
            // stage: regs -> smem (warp w writes code w+4i, lanes = float4 qq)
#pragma unroll
            for (int i = 0; i < 8; i++)
                *(float4*)&cs[(w + 4 * i) * RST + 4 * l] = v[i];
#pragma unroll
            for (int i = 0; i < 8; i++)
                if (l == i) e2s[w + 4 * i] = e2v[i];
            // prefetch next chunk (overlaps with compute below)
            {
                const float4* nsrc = 0;
                if (c + 1 < NCH)        nsrc = cbl4 + (size_t)(c + 1) * TKC * D4;
                else if (lvl + 1 < MLVL) nsrc = cb4 + (size_t)(lvl + 1) * KC * D4;
                if (nsrc) {
#pragma unroll
                    for (int i = 0; i < 8; i++) v[i] = nsrc[t + NTHR * i];
                }
            }
            __syncthreads();

            // ---- dot accumulation: f32x2 pairs along d, zero MOVs ----
            unsigned long long acc[4][4];
#pragma unroll
            for (int i = 0; i < 4; i++)
#pragma unroll
                for (int j = 0; j < 4; j++) acc[i][j] = 0ull;

#pragma unroll 8
            for (int q = 0; q < D4; q++) {
                ulonglong2 rv[4], cv[4];
#pragma unroll
                for (int i = 0; i < 4; i++) rv[i] = rvp[i * 33 + q];
#pragma unroll
                for (int j = 0; j < 4; j++) cv[j] = cvp[j * 132 + q];
#pragma unroll
                for (int i = 0; i < 4; i++)
#pragma unroll
                    for (int j = 0; j < 4; j++) {
                        fma2(acc[i][j], rv[i].x, cv[j].x);
                        fma2(acc[i][j], rv[i].y, cv[j].y);
                    }
            }

            // ---- distances + running argmin (ascending k, strict <) ----
#pragma unroll
            for (int j = 0; j < 4; j++) {
                int kk = kbase + txc + 4 * j;
                float e2k = e2s[kk];
                int kg = c * TKC + kk;
#pragma unroll
                for (int i = 0; i < 4; i++) {
                    float lo, hi;
                    unpack2(acc[i][j], lo, hi);
                    float dot = __fadd_rn(lo, hi);
                    float s = __fadd_rn(r2r[i], e2k);
                    float dv = __fmaf_rn(-2.0f, dot, s);
                    if (dv < bd[i]) { bd[i] = dv; bi[i] = kg; }
                }
            }
        }

        // ---- argmin across txc lanes (first-min via index tiebreak) ----
#pragma unroll
        for (int off = 1; off <= 2; off <<= 1)
#pragma unroll
            for (int i = 0; i < 4; i++) {
                float od = __shfl_xor_sync(0xffffffffu, bd[i], off);
                int   oi = __shfl_xor_sync(0xffffffffu, bi[i], off);
                if (od < bd[i] || (od == bd[i] && oi < bi[i])) { bd[i] = od; bi[i] = oi; }
            }
        if (txc == 0)
#pragma unroll
            for (int i = 0; i < 4; i++) {
                sd[half * TM + 4 * rowg + i] = bd[i];
                si[half * TM + 4 * rowg + i] = bi[i];
            }
        __syncthreads();
        if (t < TM) {
            float d0 = sd[t], d1 = sd[TM + t];
            int   i0 = si[t], i1 = si[TM + t];
            idxs[lvl * TM + t] = (d1 < d0 || (d1 == d0 && i1 < i0)) ? i1 : i0;
        }
        __syncthreads();

        // ---- residual update + r2 + loss partial ----
#pragma unroll
        for (int i2 = 0; i2 < 16; i2++) {
            int row = w + 4 * i2;
            int qi = idxs[lvl * TM + row];
            float4 qv = cbl4[(size_t)qi * D4 + l];
            float* rp = &rs[row * RST + 4 * l];
            float4 rv = *(float4*)rp;
            rv.x = __fsub_rn(rv.x, qv.x);
            rv.y = __fsub_rn(rv.y, qv.y);
            rv.z = __fsub_rn(rv.z, qv.z);
            rv.w = __fsub_rn(rv.w, qv.w);
            *(float4*)rp = rv;
            float p = __fmaf_rn(rv.x, rv.x, 0.f);
            p = __fmaf_rn(rv.y, rv.y, p);
            p = __fmaf_rn(rv.z, rv.z, p);
            p = __fmaf_rn(rv.w, rv.w, p);
            lsum += (double)p;               // (q - r_pre)^2 == r_post^2
#pragma unroll
            for (int off = 16; off >= 1; off >>= 1)
                p = __fadd_rn(p, __shfl_xor_sync(0xffffffffu, p, off));
            if (l == 0) r2s[row] = p;
        }
        __syncthreads();
    }

    // ---- y = x + (q_sum - x), reference rounding chain ----
    {
        float4* y4 = (float4*)(y + (size_t)rowBase * D);
#pragma unroll
        for (int i2 = 0; i2 < 16; i2++) {
            int row = w + 4 * i2;
            int a0 = idxs[0 * TM + row], a1 = idxs[1 * TM + row];
            int a2 = idxs[2 * TM + row], a3 = idxs[3 * TM + row];
            float4 q0 = cb4[((size_t)0 * KC + a0) * D4 + l];
            float4 q1 = cb4[((size_t)1 * KC + a1) * D4 + l];
            float4 q2 = cb4[((size_t)2 * KC + a2) * D4 + l];
            float4 q3 = cb4[((size_t)3 * KC + a3) * D4 + l];
            float4 xv = x4[(size_t)row * D4 + l];
            float4 o;
            o.x = __fadd_rn(xv.x, __fsub_rn(__fadd_rn(__fadd_rn(__fadd_rn(q0.x, q1.x), q2.x), q3.x), xv.x));
            o.y = __fadd_rn(xv.y, __fsub_rn(__fadd_rn(__fadd_rn(__fadd_rn(q0.y, q1.y), q2.y), q3.y), xv.y));
            o.z = __fadd_rn(xv.z, __fsub_rn(__fadd_rn(__fadd_rn(__fadd_rn(q0.z, q1.z), q2.z), q3.z), xv.z));
            o.w = __fadd_rn(xv.w, __fsub_rn(__fadd_rn(__fadd_rn(__fadd_rn(q0.w, q1.w), q2.w), q3.w), xv.w));
            y4[(size_t)row * D4 + l] = o;
        }
    }

    // ---- deterministic block loss reduction ----
    dred[t] = lsum;
    __syncthreads();
#pragma unroll
    for (int s = NTHR / 2; s > 0; s >>= 1) {
        if (t < s) dred[t] += dred[t + s];
        __syncthreads();
    }
    if (t == 0) g_part[blockIdx.x] = dred[0];
}

__global__ void loss_kernel(float* out, int nblocks, long long nelems) {
    __shared__ double sh[128];
    double s = 0.0;
    for (int b = threadIdx.x; b < nblocks; b += 128) s += g_part[b];
    sh[threadIdx.x] = s;
    __syncthreads();
    for (int st = 64; st > 0; st >>= 1) {
        if (threadIdx.x < st) sh[threadIdx.x] += sh[threadIdx.x + st];
        __syncthreads();
    }
    if (threadIdx.x == 0)
        out[0] = (float)(1.25 * (sh[0] / (double)nelems));
}

extern "C" void kernel_launch(void* const* d_in, const int* in_sizes, int n_in,
                              void* d_out, int out_size) {
    const float* x  = (const float*)d_in[0];
    const float* cb = (const float*)d_in[1];
    float* y = (float*)d_out;

    const long long xelems = (long long)in_sizes[0];
    const int nrows   = (int)(xelems / D);
    const int nblocks = (nrows + TM - 1) / TM;

    cudaFuncSetAttribute(rvq_kernel, cudaFuncAttributeMaxDynamicSharedMemorySize, SMEM_BYTES);

    rvq_kernel<<<nblocks, NTHR, SMEM_BYTES>>>(x, cb, y, nrows);
    if ((long long)out_size > xelems)
        loss_kernel<<<1, 128>>>(y + xelems, nblocks, xelems);
}

// round 5
// speedup vs baseline: 2.8139x; 1.1259x over previous
#include <cuda_runtime.h>
#include <cstdint>

#define D      128
#define D4     32
#define KC     1024
#define MLVL   4
#define TM     64          // rows per block
#define TKC    32          // codes per chunk
#define NCH    (KC / TKC)  // 32
#define NTHR   128
#define RST    132         // padded row stride (floats)
#define MAXBLK 4096

__device__ double g_part[MAXBLK];

// smem layout (float offsets)
#define OFF_CS   (TM * RST)                 // 8448
#define OFF_E2S  (OFF_CS + TKC * RST)       // 12672
#define OFF_R2S  (OFF_E2S + TKC)            // 12704
#define OFF_SD   (OFF_R2S + TM)             // 12768
#define OFF_SI   (OFF_SD + 2 * TM)          // 12896
#define OFF_IDX  (OFF_SI + 2 * TM)          // 13024
#define SMEM_FLOATS (OFF_IDX + MLVL * TM)   // 13280
#define SMEM_BYTES  (SMEM_FLOATS * 4 + NTHR * 8)  // 54144

__device__ __forceinline__ void fma2(unsigned long long& acc,
                                     unsigned long long a,
                                     unsigned long long b) {
    asm("fma.rn.f32x2 %0, %1, %2, %3;" : "=l"(acc) : "l"(a), "l"(b), "l"(acc));
}
__device__ __forceinline__ void unpack2(unsigned long long v, float& lo, float& hi) {
    asm("mov.b64 {%0, %1}, %2;" : "=f"(lo), "=f"(hi) : "l"(v));
}

__global__ __launch_bounds__(NTHR, 4)
void rvq_kernel(const float* __restrict__ x, const float* __restrict__ cb,
                float* __restrict__ y, int nrows) {
    extern __shared__ float smem[];
    float* rs   = smem;                     // [TM][RST]
    float* cs   = smem + OFF_CS;            // [TKC][RST]
    float* e2s  = smem + OFF_E2S;           // [TKC]
    float* r2s  = smem + OFF_R2S;           // [TM]
    float* sd   = smem + OFF_SD;            // [2][TM]
    int*   si   = (int*)(smem + OFF_SI);    // [2][TM]
    int*   idxs = (int*)(smem + OFF_IDX);   // [MLVL][TM]
    double* dred = (double*)(smem + SMEM_FLOATS);  // [NTHR]

    const int t    = threadIdx.x;
    const int w    = t >> 5;
    const int l    = t & 31;
    const int ty   = l >> 2;               // 0..7
    const int txc  = l & 3;                // 0..3
    const int half = w & 1;
    const int rowg = 8 * (w >> 1) + ty;    // 0..15 -> rows rowg + 16*i  (i=0..3)
    const int kbase = 16 * half;

    const int rowBase = blockIdx.x * TM;
    if (rowBase >= nrows) return;
    const float4* x4  = (const float4*)(x + (size_t)rowBase * D);
    const float4* cb4 = (const float4*)cb;

    double lsum = 0.0;

    // ---- initial residual load + r2 ----
#pragma unroll
    for (int i2 = 0; i2 < 16; i2++) {
        int row = w + 4 * i2;
        float4 v = x4[(size_t)row * D4 + l];
        *(float4*)&rs[row * RST + 4 * l] = v;
        float p = __fmaf_rn(v.x, v.x, 0.f);
        p = __fmaf_rn(v.y, v.y, p);
        p = __fmaf_rn(v.z, v.z, p);
        p = __fmaf_rn(v.w, v.w, p);
#pragma unroll
        for (int off = 16; off >= 1; off >>= 1)
            p = __fadd_rn(p, __shfl_xor_sync(0xffffffffu, p, off));
        if (l == 0) r2s[row] = p;
    }
    __syncthreads();

    // rows for this thread: rowg + 16*i  -> lane stride = 1 row = 132 banks ≡ 4 mod 32
    // => the 8 ty-groups hit bank-quads 0,4,...,28: conflict-free LDS.128
    const ulonglong2* rvp = (const ulonglong2*)&rs[rowg * RST];
    const ulonglong2* cvp = (const ulonglong2*)&cs[(kbase + txc) * RST];

    // ---- prefetch chunk (lvl=0, c=0) into registers ----
    float4 v[8];
#pragma unroll
    for (int i = 0; i < 8; i++) v[i] = cb4[t + NTHR * i];

    for (int lvl = 0; lvl < MLVL; lvl++) {
        const float4* cbl4 = cb4 + (size_t)lvl * KC * D4;

        float r2r[4];
#pragma unroll
        for (int i = 0; i < 4; i++) r2r[i] = r2s[rowg + 16 * i];

        float bd[4]; int bi[4];
#pragma unroll
        for (int i = 0; i < 4; i++) { bd[i] = 3.4e38f; bi[i] = 0; }

        for (int c = 0; c < NCH; c++) {
            // e2 for codes w+4i from prefetched regs
            float e2v[8];
#pragma unroll
            for (int i = 0; i < 8; i++) {
                float p = __fmaf_rn(v[i].x, v[i].x, 0.f);
                p = __fmaf_rn(v[i].y, v[i].y, p);
                p = __fmaf_rn(v[i].z, v[i].z, p);
                p = __fmaf_rn(v[i].w, v[i].w, p);
#pragma unroll
                for (int off = 16; off >= 1; off >>= 1)
                    p = __fadd_rn(p, __shfl_xor_sync(0xffffffffu, p, off));
                e2v[i] = p;
            }
            __syncthreads();     // previous chunk compute done -> cs/e2s free
#pragma unroll
            for (int i = 0; i < 8; i++)
                *(float4*)&cs[(w + 4 * i) * RST + 4 * l] = v[i];
#pragma unroll
            for (int i = 0; i < 8; i++)
                if (l == i) e2s[w + 4 * i] = e2v[i];
            // prefetch next chunk (overlaps compute)
            {
                const float4* nsrc = 0;
                if (c + 1 < NCH)         nsrc = cbl4 + (size_t)(c + 1) * TKC * D4;
                else if (lvl + 1 < MLVL) nsrc = cb4 + (size_t)(lvl + 1) * KC * D4;
                if (nsrc) {
#pragma unroll
                    for (int i = 0; i < 8; i++) v[i] = nsrc[t + NTHR * i];
                }
            }
            __syncthreads();

            // ---- dot accumulation: f32x2 pairs along d, zero MOVs, conflict-free ----
            unsigned long long acc[4][4];
#pragma unroll
            for (int i = 0; i < 4; i++)
#pragma unroll
                for (int j = 0; j < 4; j++) acc[i][j] = 0ull;

#pragma unroll 8
            for (int q = 0; q < D4; q++) {
                ulonglong2 rv[4], cv[4];
#pragma unroll
                for (int i = 0; i < 4; i++) rv[i] = rvp[i * 528 + q];   // 16 rows * 33 u2
#pragma unroll
                for (int j = 0; j < 4; j++) cv[j] = cvp[j * 132 + q];   // 4 codes * 33 u2
#pragma unroll
                for (int i = 0; i < 4; i++)
#pragma unroll
                    for (int j = 0; j < 4; j++) {
                        fma2(acc[i][j], rv[i].x, cv[j].x);
                        fma2(acc[i][j], rv[i].y, cv[j].y);
                    }
            }

            // ---- distances + running argmin (ascending k, strict <) ----
#pragma unroll
            for (int j = 0; j < 4; j++) {
                int kk = kbase + txc + 4 * j;
                float e2k = e2s[kk];
                int kg = c * TKC + kk;
#pragma unroll
                for (int i = 0; i < 4; i++) {
                    float lo, hi;
                    unpack2(acc[i][j], lo, hi);
                    float dot = __fadd_rn(lo, hi);
                    float s = __fadd_rn(r2r[i], e2k);
                    float dv = __fmaf_rn(-2.0f, dot, s);
                    if (dv < bd[i]) { bd[i] = dv; bi[i] = kg; }
                }
            }
        }

        // ---- argmin across txc lanes (first-min via index tiebreak) ----
#pragma unroll
        for (int off = 1; off <= 2; off <<= 1)
#pragma unroll
            for (int i = 0; i < 4; i++) {
                float od = __shfl_xor_sync(0xffffffffu, bd[i], off);
                int   oi = __shfl_xor_sync(0xffffffffu, bi[i], off);
                if (od < bd[i] || (od == bd[i] && oi < bi[i])) { bd[i] = od; bi[i] = oi; }
            }
        if (txc == 0)
#pragma unroll
            for (int i = 0; i < 4; i++) {
                sd[half * TM + rowg + 16 * i] = bd[i];
                si[half * TM + rowg + 16 * i] = bi[i];
            }
        __syncthreads();
        if (t < TM) {
            float d0 = sd[t], d1 = sd[TM + t];
            int   i0 = si[t], i1 = si[TM + t];
            idxs[lvl * TM + t] = (d1 < d0 || (d1 == d0 && i1 < i0)) ? i1 : i0;
        }
        __syncthreads();

        // ---- residual update + r2 + loss partial ----
#pragma unroll
        for (int i2 = 0; i2 < 16; i2++) {
            int row = w + 4 * i2;
            int qi = idxs[lvl * TM + row];
            float4 qv = cbl4[(size_t)qi * D4 + l];
            float* rp = &rs[row * RST + 4 * l];
            float4 rv = *(float4*)rp;
            rv.x = __fsub_rn(rv.x, qv.x);
            rv.y = __fsub_rn(rv.y, qv.y);
            rv.z = __fsub_rn(rv.z, qv.z);
            rv.w = __fsub_rn(rv.w, qv.w);
            *(float4*)rp = rv;
            float p = __fmaf_rn(rv.x, rv.x, 0.f);
            p = __fmaf_rn(rv.y, rv.y, p);
            p = __fmaf_rn(rv.z, rv.z, p);
            p = __fmaf_rn(rv.w, rv.w, p);
            lsum += (double)p;               // (q - r_pre)^2 == r_post^2
#pragma unroll
            for (int off = 16; off >= 1; off >>= 1)
                p = __fadd_rn(p, __shfl_xor_sync(0xffffffffu, p, off));
            if (l == 0) r2s[row] = p;
        }
        __syncthreads();
    }

    // ---- y = x + (q_sum - x), reference rounding chain ----
    {
        float4* y4 = (float4*)(y + (size_t)rowBase * D);
#pragma unroll
        for (int i2 = 0; i2 < 16; i2++) {
            int row = w + 4 * i2;
            int a0 = idxs[0 * TM + row], a1 = idxs[1 * TM + row];
            int a2 = idxs[2 * TM + row], a3 = idxs[3 * TM + row];
            float4 q0 = cb4[((size_t)0 * KC + a0) * D4 + l];
            float4 q1 = cb4[((size_t)1 * KC + a1) * D4 + l];
            float4 q2 = cb4[((size_t)2 * KC + a2) * D4 + l];
            float4 q3 = cb4[((size_t)3 * KC + a3) * D4 + l];
            float4 xv = x4[(size_t)row * D4 + l];
            float4 o;
            o.x = __fadd_rn(xv.x, __fsub_rn(__fadd_rn(__fadd_rn(__fadd_rn(q0.x, q1.x), q2.x), q3.x), xv.x));
            o.y = __fadd_rn(xv.y, __fsub_rn(__fadd_rn(__fadd_rn(__fadd_rn(q0.y, q1.y), q2.y), q3.y), xv.y));
            o.z = __fadd_rn(xv.z, __fsub_rn(__fadd_rn(__fadd_rn(__fadd_rn(q0.z, q1.z), q2.z), q3.z), xv.z));
            o.w = __fadd_rn(xv.w, __fsub_rn(__fadd_rn(__fadd_rn(__fadd_rn(q0.w, q1.w), q2.w), q3.w), xv.w));
            y4[(size_t)row * D4 + l] = o;
        }
    }

    // ---- deterministic block loss reduction ----
    dred[t] = lsum;
    __syncthreads();
#pragma unroll
    for (int s = NTHR / 2; s > 0; s >>= 1) {
        if (t < s) dred[t] += dred[t + s];
        __syncthreads();
    }
    if (t == 0) g_part[blockIdx.x] = dred[0];
}

__global__ void loss_kernel(float* out, int nblocks, long long nelems) {
    __shared__ double sh[128];
    double s = 0.0;
    for (int b = threadIdx.x; b < nblocks; b += 128) s += g_part[b];
    sh[threadIdx.x] = s;
    __syncthreads();
    for (int st = 64; st > 0; st >>= 1) {
        if (threadIdx.x < st) sh[threadIdx.x] += sh[threadIdx.x + st];
        __syncthreads();
    }
    if (threadIdx.x == 0)
        out[0] = (float)(1.25 * (sh[0] / (double)nelems));
}

extern "C" void kernel_launch(void* const* d_in, const int* in_sizes, int n_in,
                              void* d_out, int out_size) {
    const float* x  = (const float*)d_in[0];
    const float* cb = (const float*)d_in[1];
    float* y = (float*)d_out;

    const long long xelems = (long long)in_sizes[0];
    const int nrows   = (int)(xelems / D);
    const int nblocks = (nrows + TM - 1) / TM;

    cudaFuncSetAttribute(rvq_kernel, cudaFuncAttributeMaxDynamicSharedMemorySize, SMEM_BYTES);

    rvq_kernel<<<nblocks, NTHR, SMEM_BYTES>>>(x, cb, y, nrows);
    if ((long long)out_size > xelems)
        loss_kernel<<<1, 128>>>(y + xelems, nblocks, xelems);
}

// round 6
// speedup vs baseline: 3.2552x; 1.1568x over previous
#include <cuda_runtime.h>
#include <cstdint>

#define D      128
#define D4     32
#define KC     1024
#define MLVL   4
#define TM     128         // rows per block
#define TKC    64          // codes per chunk
#define NCH    (KC / TKC)  // 16
#define NTHR   128
#define RST    132         // padded row stride (floats)
#define MAXBLK 4096

__device__ float  g_e2[MLVL * KC];
__device__ double g_part[MAXBLK];

// smem layout (float offsets)
#define OFF_CS   (TM * RST)                 // 16896
#define OFF_E2   (OFF_CS + TKC * RST)       // 25344
#define OFF_R2S  (OFF_E2 + KC)              // 26368
#define OFF_IDX  (OFF_R2S + TM)             // 26496
#define SMEM_FLOATS (OFF_IDX + MLVL * TM)   // 27008
#define SMEM_BYTES  (SMEM_FLOATS * 4 + NTHR * 8)  // 109056

__device__ __forceinline__ void fma2(unsigned long long& acc,
                                     unsigned long long a,
                                     unsigned long long b) {
    asm("fma.rn.f32x2 %0, %1, %2, %3;" : "=l"(acc) : "l"(a), "l"(b), "l"(acc));
}
__device__ __forceinline__ void unpack2(unsigned long long v, float& lo, float& hi) {
    asm("mov.b64 {%0, %1}, %2;" : "=f"(lo), "=f"(hi) : "l"(v));
}
__device__ __forceinline__ void cp_async16(void* smem_dst, const void* gsrc) {
    unsigned saddr = (unsigned)__cvta_generic_to_shared(smem_dst);
    asm volatile("cp.async.ca.shared.global [%0], [%1], 16;" :: "r"(saddr), "l"(gsrc));
}

// ---- e2[k] = sum_d cb[k][d]^2, warp per code, coalesced ----
__global__ void e2_kernel(const float* __restrict__ cb) {
    int code = blockIdx.x * 4 + (threadIdx.x >> 5);
    int l = threadIdx.x & 31;
    const float4* row = (const float4*)(cb + (size_t)code * D);
    float4 v = row[l];
    float p = __fmaf_rn(v.x, v.x, 0.f);
    p = __fmaf_rn(v.y, v.y, p);
    p = __fmaf_rn(v.z, v.z, p);
    p = __fmaf_rn(v.w, v.w, p);
#pragma unroll
    for (int off = 16; off >= 1; off >>= 1)
        p = __fadd_rn(p, __shfl_xor_sync(0xffffffffu, p, off));
    if (l == 0) g_e2[code] = p;
}

__global__ __launch_bounds__(NTHR, 2)
void rvq_kernel(const float* __restrict__ x, const float* __restrict__ cb,
                float* __restrict__ y, int nrows) {
    extern __shared__ float smem[];
    float* rs    = smem;                    // [TM][RST]
    float* cs    = smem + OFF_CS;           // [TKC][RST]
    float* e2all = smem + OFF_E2;           // [KC]
    float* r2s   = smem + OFF_R2S;          // [TM]
    int*   idxs  = (int*)(smem + OFF_IDX);  // [MLVL][TM]
    double* dred = (double*)(smem + SMEM_FLOATS);  // [NTHR]

    const int t    = threadIdx.x;
    const int w    = t >> 5;
    const int l    = t & 31;
    const int rowg = t >> 3;               // 0..15 -> rows rowg + 16*i (i=0..7)
    const int txc  = t & 7;                // 0..7  -> codes txc + 8*j (j=0..7)

    const int rowBase = blockIdx.x * TM;
    if (rowBase >= nrows) return;
    const float4* x4  = (const float4*)(x + (size_t)rowBase * D);
    const float4* cb4 = (const float4*)cb;

    double lsum = 0.0;

    // ---- initial residual load + r2 ----
#pragma unroll
    for (int i2 = 0; i2 < 32; i2++) {
        int row = w + 4 * i2;
        float4 v = x4[(size_t)row * D4 + l];
        *(float4*)&rs[row * RST + 4 * l] = v;
        float p = __fmaf_rn(v.x, v.x, 0.f);
        p = __fmaf_rn(v.y, v.y, p);
        p = __fmaf_rn(v.z, v.z, p);
        p = __fmaf_rn(v.w, v.w, p);
#pragma unroll
        for (int off = 16; off >= 1; off >>= 1)
            p = __fadd_rn(p, __shfl_xor_sync(0xffffffffu, p, off));
        if (l == 0) r2s[row] = p;
    }
    __syncthreads();

    const ulonglong2* rvp = (const ulonglong2*)&rs[rowg * RST];   // rows: +528*i
    const ulonglong2* cvp = (const ulonglong2*)&cs[txc * RST];    // codes: +264*j

    for (int lvl = 0; lvl < MLVL; lvl++) {
        const float4* cbl4 = cb4 + (size_t)lvl * KC * D4;

        // stage this level's e2 (sync'd by the first chunk barrier)
        {
            const float4* e2src = (const float4*)(g_e2 + lvl * KC);
            float4 a = e2src[t];
            float4 b = e2src[t + NTHR];
            *(float4*)&e2all[4 * t] = a;
            *(float4*)&e2all[4 * (t + NTHR)] = b;
        }

        float r2r[8];
#pragma unroll
        for (int i = 0; i < 8; i++) r2r[i] = r2s[rowg + 16 * i];

        float bd[8]; int bi[8];
#pragma unroll
        for (int i = 0; i < 8; i++) { bd[i] = 3.4e38f; bi[i] = 0; }

        for (int c = 0; c < NCH; c++) {
            __syncthreads();   // previous chunk compute done -> cs free (also fences e2all)
            // ---- stage chunk via cp.async (coalesced, conflict-free STS) ----
            {
                const float4* src = cbl4 + (size_t)c * TKC * D4;
#pragma unroll
                for (int ii = 0; ii < 16; ii++) {
                    int e = t + NTHR * ii;           // 0..2047
                    int k = e >> 5, qq = e & 31;
                    cp_async16(&cs[k * RST + 4 * qq], src + e);
                }
                asm volatile("cp.async.commit_group;");
                asm volatile("cp.async.wait_group 0;");
            }
            __syncthreads();

            // ---- 8x8 register tile dot accumulation ----
            unsigned long long acc[8][8];
#pragma unroll
            for (int i = 0; i < 8; i++)
#pragma unroll
                for (int j = 0; j < 8; j++) acc[i][j] = 0ull;

            for (int q = 0; q < D4; q++) {
                ulonglong2 rv[8];
#pragma unroll
                for (int i = 0; i < 8; i++) rv[i] = rvp[528 * i + q];
#pragma unroll
                for (int j = 0; j < 8; j++) {
                    ulonglong2 cv = cvp[264 * j + q];
#pragma unroll
                    for (int i = 0; i < 8; i++) {
                        fma2(acc[i][j], rv[i].x, cv.x);
                        fma2(acc[i][j], rv[i].y, cv.y);
                    }
                }
            }

            // ---- distances + running argmin (ascending k, strict <) ----
#pragma unroll
            for (int j = 0; j < 8; j++) {
                int kk = txc + 8 * j;
                float e2k = e2all[c * TKC + kk];
                int kg = c * TKC + kk;
#pragma unroll
                for (int i = 0; i < 8; i++) {
                    float lo, hi;
                    unpack2(acc[i][j], lo, hi);
                    float dot = __fadd_rn(lo, hi);
                    float s = __fadd_rn(r2r[i], e2k);
                    float dv = __fmaf_rn(-2.0f, dot, s);
                    if (dv < bd[i]) { bd[i] = dv; bi[i] = kg; }
                }
            }
        }

        // ---- argmin across the 8 txc lanes (first-min via index tiebreak) ----
#pragma unroll
        for (int off = 1; off <= 4; off <<= 1)
#pragma unroll
            for (int i = 0; i < 8; i++) {
                float od = __shfl_xor_sync(0xffffffffu, bd[i], off);
                int   oi = __shfl_xor_sync(0xffffffffu, bi[i], off);
                if (od < bd[i] || (od == bd[i] && oi < bi[i])) { bd[i] = od; bi[i] = oi; }
            }
        if (txc == 0)
#pragma unroll
            for (int i = 0; i < 8; i++)
                idxs[lvl * TM + rowg + 16 * i] = bi[i];
        __syncthreads();

        // ---- residual update + r2 + loss partial ----
#pragma unroll
        for (int i2 = 0; i2 < 32; i2++) {
            int row = w + 4 * i2;
            int qi = idxs[lvl * TM + row];
            float4 qv = cbl4[(size_t)qi * D4 + l];
            float* rp = &rs[row * RST + 4 * l];
            float4 rv = *(float4*)rp;
            rv.x = __fsub_rn(rv.x, qv.x);
            rv.y = __fsub_rn(rv.y, qv.y);
            rv.z = __fsub_rn(rv.z, qv.z);
            rv.w = __fsub_rn(rv.w, qv.w);
            *(float4*)rp = rv;
            float p = __fmaf_rn(rv.x, rv.x, 0.f);
            p = __fmaf_rn(rv.y, rv.y, p);
            p = __fmaf_rn(rv.z, rv.z, p);
            p = __fmaf_rn(rv.w, rv.w, p);
            lsum += (double)p;               // (q - r_pre)^2 == r_post^2
#pragma unroll
            for (int off = 16; off >= 1; off >>= 1)
                p = __fadd_rn(p, __shfl_xor_sync(0xffffffffu, p, off));
            if (l == 0) r2s[row] = p;
        }
        __syncthreads();
    }

    // ---- y = x + (q_sum - x), reference rounding chain ----
    {
        float4* y4 = (float4*)(y + (size_t)rowBase * D);
#pragma unroll
        for (int i2 = 0; i2 < 32; i2++) {
            int row = w + 4 * i2;
            int a0 = idxs[0 * TM + row], a1 = idxs[1 * TM + row];
            int a2 = idxs[2 * TM + row], a3 = idxs[3 * TM + row];
            float4 q0 = cb4[((size_t)0 * KC + a0) * D4 + l];
            float4 q1 = cb4[((size_t)1 * KC + a1) * D4 + l];
            float4 q2 = cb4[((size_t)2 * KC + a2) * D4 + l];
            float4 q3 = cb4[((size_t)3 * KC + a3) * D4 + l];
            float4 xv = x4[(size_t)row * D4 + l];
            float4 o;
            o.x = __fadd_rn(xv.x, __fsub_rn(__fadd_rn(__fadd_rn(__fadd_rn(q0.x, q1.x), q2.x), q3.x), xv.x));
            o.y = __fadd_rn(xv.y, __fsub_rn(__fadd_rn(__fadd_rn(__fadd_rn(q0.y, q1.y), q2.y), q3.y), xv.y));
            o.z = __fadd_rn(xv.z, __fsub_rn(__fadd_rn(__fadd_rn(__fadd_rn(q0.z, q1.z), q2.z), q3.z), xv.z));
            o.w = __fadd_rn(xv.w, __fsub_rn(__fadd_rn(__fadd_rn(__fadd_rn(q0.w, q1.w), q2.w), q3.w), xv.w));
            y4[(size_t)row * D4 + l] = o;
        }
    }

    // ---- deterministic block loss reduction ----
    dred[t] = lsum;
    __syncthreads();
#pragma unroll
    for (int s = NTHR / 2; s > 0; s >>= 1) {
        if (t < s) dred[t] += dred[t + s];
        __syncthreads();
    }
    if (t == 0) g_part[blockIdx.x] = dred[0];
}

__global__ void loss_kernel(float* out, int nblocks, long long nelems) {
    __shared__ double sh[128];
    double s = 0.0;
    for (int b = threadIdx.x; b < nblocks; b += 128) s += g_part[b];
    sh[threadIdx.x] = s;
    __syncthreads();
    for (int st = 64; st > 0; st >>= 1) {
        if (threadIdx.x < st) sh[threadIdx.x] += sh[threadIdx.x + st];
        __syncthreads();
    }
    if (threadIdx.x == 0)
        out[0] = (float)(1.25 * (sh[0] / (double)nelems));
}

extern "C" void kernel_launch(void* const* d_in, const int* in_sizes, int n_in,
                              void* d_out, int out_size) {
    const float* x  = (const float*)d_in[0];
    const float* cb = (const float*)d_in[1];
    float* y = (float*)d_out;

    const long long xelems = (long long)in_sizes[0];
    const int nrows   = (int)(xelems / D);
    const int nblocks = (nrows + TM - 1) / TM;

    cudaFuncSetAttribute(rvq_kernel, cudaFuncAttributeMaxDynamicSharedMemorySize, SMEM_BYTES);

    e2_kernel<<<MLVL * KC / 4, 128>>>(cb);
    rvq_kernel<<<nblocks, NTHR, SMEM_BYTES>>>(x, cb, y, nrows);
    if ((long long)out_size > xelems)
        loss_kernel<<<1, 128>>>(y + xelems, nblocks, xelems);
}

// round 7
// speedup vs baseline: 3.3923x; 1.0421x over previous
#include <cuda_runtime.h>
#include <cstdint>

#define D      128
#define D4     32
#define KC     1024
#define MLVL   4
#define TM     128         // rows per block
#define TKC    64          // codes per chunk
#define NCH    (KC / TKC)  // 16
#define NTHR   128
#define RST    132         // padded row stride (floats)

__device__ float              g_e2[MLVL * KC];
__device__ unsigned long long g_lsum  = 0ULL;
__device__ unsigned int       g_count = 0u;

// smem layout (float offsets)
#define OFF_CS   (TM * RST)                 // 16896
#define OFF_E2   (OFF_CS + TKC * RST)       // 25344
#define OFF_R2S  (OFF_E2 + KC)              // 26368
#define OFF_IDX  (OFF_R2S + TM)             // 26496
#define SMEM_FLOATS (OFF_IDX + MLVL * TM)   // 27008
#define SMEM_BYTES  (SMEM_FLOATS * 4)       // 108032

#define LSCALE 17179869184.0                // 2^34

__device__ __forceinline__ void fma2(unsigned long long& acc,
                                     unsigned long long a,
                                     unsigned long long b) {
    asm("fma.rn.f32x2 %0, %1, %2, %3;" : "=l"(acc) : "l"(a), "l"(b), "l"(acc));
}
__device__ __forceinline__ void unpack2(unsigned long long v, float& lo, float& hi) {
    asm("mov.b64 {%0, %1}, %2;" : "=f"(lo), "=f"(hi) : "l"(v));
}
__device__ __forceinline__ void cp_async16(void* smem_dst, const void* gsrc) {
    unsigned saddr = (unsigned)__cvta_generic_to_shared(smem_dst);
    asm volatile("cp.async.ca.shared.global [%0], [%1], 16;" :: "r"(saddr), "l"(gsrc));
}

// ---- e2[k] = sum_d cb[k][d]^2, warp per code, coalesced ----
__global__ void e2_kernel(const float* __restrict__ cb) {
    int code = blockIdx.x * 4 + (threadIdx.x >> 5);
    int l = threadIdx.x & 31;
    const float4* row = (const float4*)(cb + (size_t)code * D);
    float4 v = row[l];
    float p = __fmaf_rn(v.x, v.x, 0.f);
    p = __fmaf_rn(v.y, v.y, p);
    p = __fmaf_rn(v.z, v.z, p);
    p = __fmaf_rn(v.w, v.w, p);
#pragma unroll
    for (int off = 16; off >= 1; off >>= 1)
        p = __fadd_rn(p, __shfl_xor_sync(0xffffffffu, p, off));
    if (l == 0) g_e2[code] = p;
}

// one pipelined q-step: consumes RV, prefetches RVN (next q), cv carried in/out
#define QSTEP(QI, RV, RVN)                                              \
    {                                                                   \
        const int qn_ = ((QI) + 1) & (D4 - 1);                          \
        _Pragma("unroll")                                               \
        for (int j = 0; j < 8; j++) {                                   \
            ulonglong2 cvN_ = (j < 7) ? cvp[264 * (j + 1) + (QI)]       \
                                      : cvp[qn_];                       \
            (RVN)[j] = rvp[528 * j + qn_];                              \
            _Pragma("unroll")                                           \
            for (int i = 0; i < 8; i++) {                               \
                fma2(acc[i][j], (RV)[i].x, cv.x);                       \
                fma2(acc[i][j], (RV)[i].y, cv.y);                       \
            }                                                           \
            cv = cvN_;                                                  \
        }                                                               \
    }

__global__ __launch_bounds__(NTHR, 2)
void rvq_kernel(const float* __restrict__ x, const float* __restrict__ cb,
                float* __restrict__ y, float* __restrict__ loss_out,
                int nrows, long long nelems) {
    extern __shared__ float smem[];
    float* rs    = smem;                    // [TM][RST]
    float* cs    = smem + OFF_CS;           // [TKC][RST]
    float* e2all = smem + OFF_E2;           // [KC]
    float* r2s   = smem + OFF_R2S;          // [TM]
    int*   idxs  = (int*)(smem + OFF_IDX);  // [MLVL][TM]

    const int t    = threadIdx.x;
    const int w    = t >> 5;
    const int l    = t & 31;
    const int rowg = t >> 3;               // 0..15 -> rows rowg + 16*i (i=0..7)
    const int txc  = t & 7;                // 0..7  -> codes txc + 8*j (j=0..7)

    const int rowBase = blockIdx.x * TM;
    if (rowBase >= nrows) return;
    const float4* x4  = (const float4*)(x + (size_t)rowBase * D);
    const float4* cb4 = (const float4*)cb;

    double lsum = 0.0;

    // ---- initial residual load + r2 ----
#pragma unroll
    for (int i2 = 0; i2 < 32; i2++) {
        int row = w + 4 * i2;
        float4 v = x4[(size_t)row * D4 + l];
        *(float4*)&rs[row * RST + 4 * l] = v;
        float p = __fmaf_rn(v.x, v.x, 0.f);
        p = __fmaf_rn(v.y, v.y, p);
        p = __fmaf_rn(v.z, v.z, p);
        p = __fmaf_rn(v.w, v.w, p);
#pragma unroll
        for (int off = 16; off >= 1; off >>= 1)
            p = __fadd_rn(p, __shfl_xor_sync(0xffffffffu, p, off));
        if (l == 0) r2s[row] = p;
    }
    __syncthreads();

    const ulonglong2* rvp = (const ulonglong2*)&rs[rowg * RST];   // rows: +528*i
    const ulonglong2* cvp = (const ulonglong2*)&cs[txc * RST];    // codes: +264*j

    for (int lvl = 0; lvl < MLVL; lvl++) {
        const float4* cbl4 = cb4 + (size_t)lvl * KC * D4;

        // stage this level's e2 (fenced by the first chunk barrier)
        {
            const float4* e2src = (const float4*)(g_e2 + lvl * KC);
            float4 a = e2src[t];
            float4 b = e2src[t + NTHR];
            *(float4*)&e2all[4 * t] = a;
            *(float4*)&e2all[4 * (t + NTHR)] = b;
        }

        float r2r[8];
#pragma unroll
        for (int i = 0; i < 8; i++) r2r[i] = r2s[rowg + 16 * i];

        float bd[8]; int bi[8];
#pragma unroll
        for (int i = 0; i < 8; i++) { bd[i] = 3.4e38f; bi[i] = 0; }

        for (int c = 0; c < NCH; c++) {
            __syncthreads();   // previous chunk compute done -> cs free (also fences e2all)
            // ---- stage chunk via cp.async (coalesced, conflict-free STS) ----
            {
                const float4* src = cbl4 + (size_t)c * TKC * D4;
#pragma unroll
                for (int ii = 0; ii < 16; ii++) {
                    int e = t + NTHR * ii;           // 0..2047
                    int k = e >> 5, qq = e & 31;
                    cp_async16(&cs[k * RST + 4 * qq], src + e);
                }
                asm volatile("cp.async.commit_group;");
                asm volatile("cp.async.wait_group 0;");
            }
            __syncthreads();

            // ---- 8x8 tile, software-pipelined (cv 1-j ahead, rv ping-pong) ----
            unsigned long long acc[8][8];
#pragma unroll
            for (int i = 0; i < 8; i++)
#pragma unroll
                for (int j = 0; j < 8; j++) acc[i][j] = 0ull;

            ulonglong2 rvA[8], rvB[8];
#pragma unroll
            for (int i = 0; i < 8; i++) rvA[i] = rvp[528 * i];
            ulonglong2 cv = cvp[0];

            for (int qq = 0; qq < D4; qq += 2) {
                QSTEP(qq,     rvA, rvB)
                QSTEP(qq + 1, rvB, rvA)
            }

            // ---- distances + running argmin (ascending k, strict <) ----
#pragma unroll
            for (int j = 0; j < 8; j++) {
                int kk = txc + 8 * j;
                float e2k = e2all[c * TKC + kk];
                int kg = c * TKC + kk;
#pragma unroll
                for (int i = 0; i < 8; i++) {
                    float lo, hi;
                    unpack2(acc[i][j], lo, hi);
                    float dot = __fadd_rn(lo, hi);
                    float s = __fadd_rn(r2r[i], e2k);
                    float dv = __fmaf_rn(-2.0f, dot, s);
                    if (dv < bd[i]) { bd[i] = dv; bi[i] = kg; }
                }
            }
        }

        // ---- argmin across the 8 txc lanes (first-min via index tiebreak) ----
#pragma unroll
        for (int off = 1; off <= 4; off <<= 1)
#pragma unroll
            for (int i = 0; i < 8; i++) {
                float od = __shfl_xor_sync(0xffffffffu, bd[i], off);
                int   oi = __shfl_xor_sync(0xffffffffu, bi[i], off);
                if (od < bd[i] || (od == bd[i] && oi < bi[i])) { bd[i] = od; bi[i] = oi; }
            }
        if (txc == 0)
#pragma unroll
            for (int i = 0; i < 8; i++)
                idxs[lvl * TM + rowg + 16 * i] = bi[i];
        __syncthreads();

        // ---- residual update + r2 + loss partial ----
#pragma unroll
        for (int i2 = 0; i2 < 32; i2++) {
            int row = w + 4 * i2;
            int qi = idxs[lvl * TM + row];
            float4 qv = cbl4[(size_t)qi * D4 + l];
            float* rp = &rs[row * RST + 4 * l];
            float4 rv = *(float4*)rp;
            rv.x = __fsub_rn(rv.x, qv.x);
            rv.y = __fsub_rn(rv.y, qv.y);
            rv.z = __fsub_rn(rv.z, qv.z);
            rv.w = __fsub_rn(rv.w, qv.w);
            *(float4*)rp = rv;
            float p = __fmaf_rn(rv.x, rv.x, 0.f);
            p = __fmaf_rn(rv.y, rv.y, p);
            p = __fmaf_rn(rv.z, rv.z, p);
            p = __fmaf_rn(rv.w, rv.w, p);
            lsum += (double)p;               // (q - r_pre)^2 == r_post^2
#pragma unroll
            for (int off = 16; off >= 1; off >>= 1)
                p = __fadd_rn(p, __shfl_xor_sync(0xffffffffu, p, off));
            if (l == 0) r2s[row] = p;
        }
        __syncthreads();
    }

    // ---- y = x + (q_sum - x), reference rounding chain ----
    {
        float4* y4 = (float4*)(y + (size_t)rowBase * D);
#pragma unroll
        for (int i2 = 0; i2 < 32; i2++) {
            int row = w + 4 * i2;
            int a0 = idxs[0 * TM + row], a1 = idxs[1 * TM + row];
            int a2 = idxs[2 * TM + row], a3 = idxs[3 * TM + row];
            float4 q0 = cb4[((size_t)0 * KC + a0) * D4 + l];
            float4 q1 = cb4[((size_t)1 * KC + a1) * D4 + l];
            float4 q2 = cb4[((size_t)2 * KC + a2) * D4 + l];
            float4 q3 = cb4[((size_t)3 * KC + a3) * D4 + l];
            float4 xv = x4[(size_t)row * D4 + l];
            float4 o;
            o.x = __fadd_rn(xv.x, __fsub_rn(__fadd_rn(__fadd_rn(__fadd_rn(q0.x, q1.x), q2.x), q3.x), xv.x));
            o.y = __fadd_rn(xv.y, __fsub_rn(__fadd_rn(__fadd_rn(__fadd_rn(q0.y, q1.y), q2.y), q3.y), xv.y));
            o.z = __fadd_rn(xv.z, __fsub_rn(__fadd_rn(__fadd_rn(__fadd_rn(q0.z, q1.z), q2.z), q3.z), xv.z));
            o.w = __fadd_rn(xv.w, __fsub_rn(__fadd_rn(__fadd_rn(__fadd_rn(q0.w, q1.w), q2.w), q3.w), xv.w));
            y4[(size_t)row * D4 + l] = o;
        }
    }

    // ---- deterministic fixed-point loss reduction (int64, replay-safe) ----
    {
        long long lv = (long long)(lsum * LSCALE);
#pragma unroll
        for (int off = 16; off >= 1; off >>= 1)
            lv += __shfl_xor_sync(0xffffffffu, lv, off);
        if (l == 0) atomicAdd(&g_lsum, (unsigned long long)lv);
        __syncthreads();
        if (t == 0) {
            __threadfence();
            unsigned int prev = atomicAdd(&g_count, 1u);
            if (prev == gridDim.x - 1) {
                unsigned long long s = atomicExch(&g_lsum, 0ULL);
                loss_out[0] = (float)(1.25 * ((double)(long long)s / LSCALE)
                                           / (double)nelems);
                atomicExch(&g_count, 0u);
            }
        }
    }
}

extern "C" void kernel_launch(void* const* d_in, const int* in_sizes, int n_in,
                              void* d_out, int out_size) {
    const float* x  = (const float*)d_in[0];
    const float* cb = (const float*)d_in[1];
    float* y = (float*)d_out;

    const long long xelems = (long long)in_sizes[0];
    const int nrows   = (int)(xelems / D);
    const int nblocks = (nrows + TM - 1) / TM;
    float* loss_out = y + xelems;

    cudaFuncSetAttribute(rvq_kernel, cudaFuncAttributeMaxDynamicSharedMemorySize, SMEM_BYTES);

    e2_kernel<<<MLVL * KC / 4, 128>>>(cb);
    rvq_kernel<<<nblocks, NTHR, SMEM_BYTES>>>(x, cb, y, loss_out, nrows, xelems);
}